// round 15
// baseline (speedup 1.0000x reference)
#include <cuda_runtime.h>
#include <cuda_fp16.h>
#include <math.h>
#include <stdint.h>

// Problem constants
#define BB   4
#define TT   4096
#define DIN  1024
#define HH   16
#define DD   64
#define MM   (BB*TT)        // 16384
#define NN   (HH*DD*2)      // 2048
#define CC   128            // scan chunks per (b,h)  (32-row chunks)
#define LL   (TT/CC)        // 32

// GEMM tiling: 256x128x64, 512 threads (16 warps, 4x4, warp tile 64x32)
#define GBM 256
#define GBN 128
#define GBK 64
#define STAGES 4
#define KITERS (DIN/GBK)    // 16
#define STAGE_BYTES 49152u  // 32KB A + 16KB B

// ---------------------------------------------------------------------------
// Scratch (device globals; no allocation allowed)
// ---------------------------------------------------------------------------
__device__ __half g_Xh[(size_t)MM * DIN];      // 32 MiB
__device__ __half g_Wt[(size_t)NN * DIN];      // 4 MiB  (transposed W: [n][k])
__device__ __half g_vh[(size_t)MM * (HH*DD)];  // 32 MiB packed relu(v) fp16
__device__ float  g_s[MM * HH];                // 1 MiB   e = exp(s) per (m,h)
__device__ float  g_cu[BB*HH*CC];
__device__ float  g_cw[BB*HH*CC*DD];           // 2 MiB

// ---------------------------------------------------------------------------
// asm helpers
// ---------------------------------------------------------------------------
__device__ __forceinline__ uint32_t smem_u32(const void* p) {
    uint32_t a;
    asm("{ .reg .u64 t; cvta.to.shared.u64 t, %1; cvt.u32.u64 %0, t; }" : "=r"(a) : "l"(p));
    return a;
}
__device__ __forceinline__ void cp16(uint32_t dst, const void* src) {
    asm volatile("cp.async.cg.shared.global [%0], [%1], 16;" :: "r"(dst), "l"(src));
}
__device__ __forceinline__ void ldm4(uint32_t* r, uint32_t addr) {
    asm volatile("ldmatrix.sync.aligned.m8n8.x4.shared.b16 {%0,%1,%2,%3}, [%4];"
                 : "=r"(r[0]), "=r"(r[1]), "=r"(r[2]), "=r"(r[3]) : "r"(addr));
}
__device__ __forceinline__ void mma16816(float* c, const uint32_t* a, const uint32_t* b) {
    asm volatile("mma.sync.aligned.m16n8k16.row.col.f32.f16.f16.f32 "
                 "{%0,%1,%2,%3}, {%4,%5,%6,%7}, {%8,%9}, {%0,%1,%2,%3};"
                 : "+f"(c[0]), "+f"(c[1]), "+f"(c[2]), "+f"(c[3])
                 : "r"(a[0]), "r"(a[1]), "r"(a[2]), "r"(a[3]), "r"(b[0]), "r"(b[1]));
}
__device__ __forceinline__ float rcp_approx(float x) {
    float r;
    asm("rcp.approx.f32 %0, %1;" : "=f"(r) : "f"(x));
    return r;
}

// ---------------------------------------------------------------------------
// Fused prep: blocks [0, 8192) convert X fp32 -> fp16 (8 floats / thread);
// blocks [8192, 10240) transpose+convert W [K][N] fp32 -> g_Wt fp16 [N][K].
// ---------------------------------------------------------------------------
__global__ __launch_bounds__(256) void convXW(const float* __restrict__ X,
                                              const float* __restrict__ W) {
    const int tid = threadIdx.x;
    if (blockIdx.x < 8192) {
        size_t i = (size_t)blockIdx.x * 256 + tid;       // < 2M
        const float4* src = (const float4*)X + i * 2;
        float4 x0 = src[0], x1 = src[1];
        __half2 h0 = __floats2half2_rn(x0.x, x0.y);
        __half2 h1 = __floats2half2_rn(x0.z, x0.w);
        __half2 h2 = __floats2half2_rn(x1.x, x1.y);
        __half2 h3 = __floats2half2_rn(x1.z, x1.w);
        uint4 o;
        o.x = *(uint32_t*)&h0; o.y = *(uint32_t*)&h1;
        o.z = *(uint32_t*)&h2; o.w = *(uint32_t*)&h3;
        ((uint4*)g_Xh)[i] = o;
    } else {
        __shared__ float tile[32][33];
        const int bw = blockIdx.x - 8192;                // < 2048
        const int n0 = (bw & 63) * 32, k0 = (bw >> 6) * 32;
        const int tx = tid & 31, ty = tid >> 5;          // 32 x 8
        for (int r = ty; r < 32; r += 8)
            tile[r][tx] = W[(size_t)(k0 + r) * NN + n0 + tx];
        __syncthreads();
        for (int r = ty; r < 32; r += 8)
            g_Wt[(size_t)(n0 + r) * DIN + k0 + tx] = __float2half(tile[tx][r]);
    }
}

// ---------------------------------------------------------------------------
// GEMM via mma.sync: kv = relu(X @ W); fused: de-interleave v (fp16, smem-
// staged coalesced store), e = exp(q.relu(k)), and per-32-row-chunk prefix
// aggregates (u = sum e, w = sum e*v) — NO max stabilization (s bounded ~±4).
// CTA 256x128x64, 512 threads, 4-stage cp.async, B-fragment double buffer.
// blockIdx.x = head h, blockIdx.y = M-tile (256 rows = 8 scan chunks).
// ---------------------------------------------------------------------------
__device__ __forceinline__ void issue_stage(uint32_t sb, int stage, int kc,
                                            int bm, int bn, int tid) {
    const uint32_t so = sb + (uint32_t)stage * STAGE_BYTES;
    const int k0 = kc * GBK;
#pragma unroll
    for (int i = 0; i < 4; i++) {                        // A: 256 rows x 128B
        int idx = tid + i * 512;
        int row = idx >> 3, ch = idx & 7;
        cp16(so + row * 128 + ((uint32_t)(ch ^ (row & 7)) << 4),
             g_Xh + (size_t)(bm + row) * DIN + k0 + ch * 8);
    }
#pragma unroll
    for (int i = 0; i < 2; i++) {                        // B: 128 rows x 128B
        int idx = tid + i * 512;
        int row = idx >> 3, ch = idx & 7;
        cp16(so + 32768u + row * 128 + ((uint32_t)(ch ^ (row & 7)) << 4),
             g_Wt + (size_t)(bn + row) * DIN + k0 + ch * 8);
    }
}

__global__ __launch_bounds__(512) void gemm_mma(const float* __restrict__ qk) {
    extern __shared__ char sm[];
    __shared__ float sred[256][4];
    __shared__ float ssm[256];
    const uint32_t sb = smem_u32(sm);
    const int tid = threadIdx.x;
    const int wid = tid >> 5, lane = tid & 31;
    const int wm = wid >> 2, wn = wid & 3;               // 4 x 4 warps
    const int h  = blockIdx.x;
    const int bn = h << 7;
    const int bm = blockIdx.y * GBM;

    float acc[4][4][4];
#pragma unroll
    for (int a = 0; a < 4; a++)
#pragma unroll
        for (int b = 0; b < 4; b++)
#pragma unroll
            for (int c = 0; c < 4; c++) acc[a][b][c] = 0.f;

    // ldmatrix per-thread geometry
    const int arow = lane & 15;
    const int asel = lane >> 4;
    const int asw  = arow & 7;
    const int brow = (lane & 7) | (((lane >> 4) & 1) << 3);
    const int bsel = (lane >> 3) & 1;
    const int bsw  = brow & 7;
    uint32_t a_off[4], b_off[2];
#pragma unroll
    for (int mt = 0; mt < 4; mt++) a_off[mt] = (uint32_t)(wm * 64 + mt * 16 + arow) * 128;
#pragma unroll
    for (int bt = 0; bt < 2; bt++) b_off[bt] = 32768u + (uint32_t)(wn * 32 + bt * 16 + brow) * 128;

    // pipeline prologue
    for (int s = 0; s < STAGES - 1; s++) {
        issue_stage(sb, s, s, bm, bn, tid);
        asm volatile("cp.async.commit_group;" ::: "memory");
    }

    for (int kc = 0; kc < KITERS; kc++) {
        asm volatile("cp.async.wait_group 2;" ::: "memory");
        __syncthreads();

        if (kc + STAGES - 1 < KITERS)
            issue_stage(sb, (kc + STAGES - 1) & (STAGES - 1), kc + STAGES - 1, bm, bn, tid);
        asm volatile("cp.async.commit_group;" ::: "memory");

        const uint32_t so = sb + (uint32_t)(kc & (STAGES - 1)) * STAGE_BYTES;
        // B-fragment double buffer: prefetch ks+1 while issuing mma for ks
        uint32_t bf[2][2][4];
#pragma unroll
        for (int bt = 0; bt < 2; bt++)
            ldm4(bf[0][bt], so + b_off[bt] + ((uint32_t)(bsel ^ bsw) << 4));
#pragma unroll
        for (int ks = 0; ks < 4; ks++) {
            uint32_t af[4][4];
#pragma unroll
            for (int mt = 0; mt < 4; mt++)
                ldm4(af[mt], so + a_off[mt] + ((uint32_t)(((ks << 1) | asel) ^ asw) << 4));
            if (ks < 3) {
#pragma unroll
                for (int bt = 0; bt < 2; bt++)
                    ldm4(bf[(ks + 1) & 1][bt],
                         so + b_off[bt] + ((uint32_t)((((ks + 1) << 1) | bsel) ^ bsw) << 4));
            }
            const uint32_t (*bcur)[4] = bf[ks & 1];
#pragma unroll
            for (int mt = 0; mt < 4; mt++) {
                mma16816(acc[mt][0], af[mt], &bcur[0][0]);
                mma16816(acc[mt][1], af[mt], &bcur[0][2]);
                mma16816(acc[mt][2], af[mt], &bcur[1][0]);
                mma16816(acc[mt][3], af[mt], &bcur[1][2]);
            }
        }
    }

    // ------------- fused epilogue -------------
    // c0,c1 = (k,v) at row gq; c2,c3 = (k,v) at row gq+8; d = wn*16+nt*4+qd
    const int gq = lane >> 2, qd = lane & 3;
    float qv[4];
#pragma unroll
    for (int nt = 0; nt < 4; nt++)
        qv[nt] = __ldg(&qk[h * DD + wn * 16 + nt * 4 + qd]);

#pragma unroll
    for (int mt = 0; mt < 4; mt++) {
        const int ml0 = wm * 64 + mt * 16 + gq;
        float s0 = 0.f, s1 = 0.f;
#pragma unroll
        for (int nt = 0; nt < 4; nt++) {
            float k0 = fmaxf(acc[mt][nt][0], 0.f), v0 = fmaxf(acc[mt][nt][1], 0.f);
            float k1 = fmaxf(acc[mt][nt][2], 0.f), v1 = fmaxf(acc[mt][nt][3], 0.f);
            s0 += qv[nt] * k0;
            s1 += qv[nt] * k1;
            acc[mt][nt][1] = v0;                 // keep relu'd v for aggregates
            acc[mt][nt][3] = v1;
        }
        s0 += __shfl_xor_sync(0xFFFFFFFF, s0, 1);
        s0 += __shfl_xor_sync(0xFFFFFFFF, s0, 2);
        s1 += __shfl_xor_sync(0xFFFFFFFF, s1, 1);
        s1 += __shfl_xor_sync(0xFFFFFFFF, s1, 2);
        if (qd == 0) {
            sred[ml0][wn]     = s0;
            sred[ml0 + 8][wn] = s1;
        }
    }
    __syncthreads();
    if (tid < 256) {
        float s = sred[tid][0] + sred[tid][1] + sred[tid][2] + sred[tid][3];
        float e = __expf(s);                     // |s| ~ <= 5, no overflow risk
        g_s[(bm + tid) * HH + h] = e;
        ssm[tid] = e;
    }
    __syncthreads();

    // ---- per-chunk prefix aggregates at 32-row granularity (pure sums) ----
#pragma unroll
    for (int half = 0; half < 2; half++) {
        const int mtA = half * 2, mtB = half * 2 + 1;
        float eA0 = ssm[wm * 64 + mtA * 16 + gq];
        float eA1 = ssm[wm * 64 + mtA * 16 + gq + 8];
        float eB0 = ssm[wm * 64 + mtB * 16 + gq];
        float eB1 = ssm[wm * 64 + mtB * 16 + gq + 8];
        float lu = eA0 + eA1 + eB0 + eB1;
        float wv[4];
#pragma unroll
        for (int nt = 0; nt < 4; nt++)
            wv[nt] = eA0 * acc[mtA][nt][1] + eA1 * acc[mtA][nt][3]
                   + eB0 * acc[mtB][nt][1] + eB1 * acc[mtB][nt][3];
#pragma unroll
        for (int mask = 4; mask <= 16; mask <<= 1) {
            lu += __shfl_xor_sync(0xFFFFFFFF, lu, mask);
#pragma unroll
            for (int nt = 0; nt < 4; nt++)
                wv[nt] += __shfl_xor_sync(0xFFFFFFFF, wv[nt], mask);
        }
        const int crow = (bm >> 5) + wm * 2 + half;        // global 32-row chunk
        const int cidx = ((crow >> 7) * HH + h) * CC + (crow & 127);
        if (gq == 0) {
#pragma unroll
            for (int nt = 0; nt < 4; nt++)
                g_cw[cidx * DD + wn * 16 + nt * 4 + qd] = wv[nt];
            if (qd == 0 && wn == 0) g_cu[cidx] = lu;
        }
    }

    // ---- stage v (fp16) into now-idle pipeline smem, then coalesced write ----
    // layout: [256 rows][72 halfs] (144B stride: 16B-aligned, bank-shift 4/row)
    __half* svh = (__half*)sm;
#pragma unroll
    for (int mt = 0; mt < 4; mt++) {
        const int ml0 = wm * 64 + mt * 16 + gq;
#pragma unroll
        for (int nt = 0; nt < 4; nt++) {
            const int dl = wn * 16 + nt * 4 + qd;
            svh[ml0 * 72 + dl]       = __float2half_rn(acc[mt][nt][1]);
            svh[(ml0 + 8) * 72 + dl] = __float2half_rn(acc[mt][nt][3]);
        }
    }
    __syncthreads();
    const uint4* src4 = (const uint4*)sm;
#pragma unroll
    for (int i = 0; i < 4; i++) {
        int idx = tid + i * 512;                 // < 2048
        int row = idx >> 3, part = idx & 7;
        *((uint4*)(g_vh + (size_t)(bm + row) * (HH*DD) + h * DD + part * 8)) =
            src4[row * 9 + part];
    }
}

// ---------------------------------------------------------------------------
// Scan phase B: exclusive prefix SUM over chunk aggregates (CC=128) — pure
// FADD, no exp. grid = B*H, 64 threads.
// ---------------------------------------------------------------------------
__global__ __launch_bounds__(64) void scanB() {
    __shared__ float scu[CC], scw[CC * DD];              // 32.5 KB
    const int bh = blockIdx.x;
    const int d  = threadIdx.x;

    for (int c = 0; c < CC; c++)
        scw[c * DD + d] = g_cw[(size_t)(bh * CC + c) * DD + d];
    scu[d]      = g_cu[bh * CC + d];
    scu[d + 64] = g_cu[bh * CC + d + 64];
    __syncthreads();

    float uC = 0.f, wC = 0.f;
    for (int c = 0; c < CC; c++) {
        const int idx = bh * CC + c;
        const float ua = scu[c];
        const float wa = scw[c * DD + d];
        g_cw[(size_t)idx * DD + d] = wC;            // exclusive prefix out
        if (d == 0) g_cu[idx] = uC;
        uC += ua;
        wC += wa;
    }
}

// ---------------------------------------------------------------------------
// Scan phase C fused with head-reduction: out[b,t,d] = sum_h w/u with
// u,w pure prefix sums (e preloaded from g_s; NO exp, NO branch in the
// inner loop). grid = (B*CC, 2) = (1024 blocks), 128 threads
// (4 h-group warps x 32 d). Wave-local slab reduced+stored in-loop.
// ---------------------------------------------------------------------------
#define SCW  8                                  // tt per wave
#define NWAVE (LL/SCW)                          // 4
#define VWAVE_HALFS (SCW * HH * 32)             // 4096 halfs = 8KB

__global__ __launch_bounds__(128) void scanCR(float* __restrict__ out) {
    extern __shared__ float dyn[];
    __half* vbuf = (__half*)dyn;                         // 2 waves x 8KB
    float*  slab = dyn + (2 * VWAVE_HALFS) / 2;          // +4096 floats: 4KB slab
    float*  s_sm = slab + 4 * SCW * 32;                  // +1024 floats: 2KB e
    const int b     = blockIdx.x / CC;
    const int c     = blockIdx.x % CC;
    const int dhalf = blockIdx.y;                        // 0 or 1
    const int tid   = threadIdx.x;
    const int hs    = tid >> 5;                          // 0..3 (warp = h-group)
    const int dl    = tid & 31;                          // local d
    const int t0    = c * LL;

    const uint32_t vbase = smem_u32(vbuf);
    const __half* vsrc = g_vh + (size_t)(b * TT + t0) * (HH*DD) + dhalf * 32;

    // issue one 8-tt wave into buffer (wv & 1): 512 cp16, 4 per thread
    auto issue_wave = [&](int wv) {
        const uint32_t bofs = (uint32_t)((wv & 1) * VWAVE_HALFS * 2);
#pragma unroll
        for (int i = 0; i < 4; i++) {
            int idx = tid + i * 128;                     // < 512
            int ttl = idx >> 6, rem = idx & 63;
            int h = rem >> 2, seg = rem & 3;
            cp16(vbase + bofs + (uint32_t)(((ttl * HH + h) * 32 + seg * 8) * 2),
                 vsrc + (size_t)(wv * SCW + ttl) * (HH*DD) + h * DD + seg * 8);
        }
        asm volatile("cp.async.commit_group;" ::: "memory");
    };

    issue_wave(0);
    issue_wave(1);

    // stage e block: contiguous 512 floats (128 float4)
    ((float4*)s_sm)[tid] = ((const float4*)(g_s + (size_t)(b * TT + t0) * HH))[tid];

    float u[4], w[4];
#pragma unroll
    for (int hi = 0; hi < 4; hi++) {
        const int h   = hs * 4 + hi;
        const int idx = (b * HH + h) * CC + c;
        u[hi] = g_cu[idx];
        w[hi] = g_cw[(size_t)idx * DD + dhalf * 32 + dl];
    }

    float* myslab = slab + hs * SCW * 32;
    for (int wv = 0; wv < NWAVE; wv++) {
        if (wv < NWAVE - 2)
            asm volatile("cp.async.wait_group 1;" ::: "memory");
        else
            asm volatile("cp.async.wait_group 0;" ::: "memory");
        __syncthreads();    // also orders prev wave's slab reads before writes

        const __half* vb = vbuf + (wv & 1) * VWAVE_HALFS;
#pragma unroll
        for (int ttl = 0; ttl < SCW; ttl++) {
            const int tt = wv * SCW + ttl;
#pragma unroll
            for (int hi = 0; hi < 4; hi++) {
                const int h = hs * 4 + hi;
                const float e = s_sm[tt * HH + h];
                const float v = __half2float(vb[(ttl * HH + h) * 32 + dl]);
                u[hi] += e;
                w[hi] += e * v;
            }
            // one rcp for all four heads: 1/ui = prod(others) * rcp(prod(all))
            const float p01 = u[0] * u[1];
            const float p23 = u[2] * u[3];
            const float rp  = rcp_approx(p01 * p23);
            float sum = (w[0] * u[1] + w[1] * u[0]) * (rp * p23)
                      + (w[2] * u[3] + w[3] * u[2]) * (rp * p01);
            myslab[ttl * 32 + dl] = sum;
        }
        __syncthreads();                                  // slab complete, vbuf free
        if (wv + 2 < NWAVE) issue_wave(wv + 2);

        // reduce this wave's slab across the 4 h-groups and store (overlaps
        // the cp.async just issued). 256 outputs, 128 threads -> 2 each.
        for (int i = tid; i < SCW * 32; i += 128) {
            const int ttl = i >> 5, dd = i & 31;
            out[((size_t)b * TT + t0 + wv * SCW + ttl) * DD + dhalf * 32 + dd] =
                slab[i] + slab[SCW*32 + i] + slab[2*SCW*32 + i] + slab[3*SCW*32 + i];
        }
    }
}

extern "C" void kernel_launch(void* const* d_in, const int* in_sizes, int n_in,
                              void* d_out, int out_size) {
    const float* X = (const float*)d_in[0];   // [B,T,DIN]
    const float* W = (const float*)d_in[1];   // [DIN, 2048]
    const float* q = (const float*)d_in[2];   // [H,D]
    float* out = (float*)d_out;               // [B,T,D]

    const int gemm_smem = STAGES * (int)STAGE_BYTES;                 // 196608
    const int scan_smem = 2 * VWAVE_HALFS * 2                        // v ring 16KB
                        + 4 * SCW * 32 * (int)sizeof(float)          // slab  4KB
                        + LL * HH * (int)sizeof(float);              // e     2KB
    cudaFuncSetAttribute(gemm_mma, cudaFuncAttributeMaxDynamicSharedMemorySize,
                         gemm_smem);
    cudaFuncSetAttribute(scanCR, cudaFuncAttributeMaxDynamicSharedMemorySize,
                         scan_smem);

    convXW<<<8192 + 2048, 256>>>(X, W);
    gemm_mma<<<dim3(HH, MM / GBM), 512, gemm_smem>>>(q);
    scanB<<<BB * HH, 64>>>();
    scanCR<<<dim3(BB * CC, 2), 128, scan_smem>>>(out);
}

// round 16
// speedup vs baseline: 1.5016x; 1.5016x over previous
#include <cuda_runtime.h>
#include <cuda_fp16.h>
#include <math.h>
#include <stdint.h>

// Problem constants
#define BB   4
#define TT   4096
#define DIN  1024
#define HH   16
#define DD   64
#define MM   (BB*TT)        // 16384
#define NN   (HH*DD*2)      // 2048
#define CC   128            // scan chunks per (b,h)  (32-row chunks)
#define LL   (TT/CC)        // 32

// GEMM tiling: 256x128x64, 512 threads (16 warps, 4x4, warp tile 64x32)
#define GBM 256
#define GBN 128
#define GBK 64
#define STAGES 4
#define KITERS (DIN/GBK)    // 16
#define STAGE_BYTES 49152u  // 32KB A + 16KB B

// ---------------------------------------------------------------------------
// Scratch (device globals; no allocation allowed)
// ---------------------------------------------------------------------------
__device__ __half g_Xh[(size_t)MM * DIN];      // 32 MiB
__device__ __half g_Wt[(size_t)NN * DIN];      // 4 MiB  (transposed W: [n][k])
__device__ __half g_vh[(size_t)MM * (HH*DD)];  // 32 MiB packed relu(v) fp16
__device__ float  g_s[MM * HH];                // 1 MiB   e = exp(s) per (m,h)
__device__ float  g_cu[BB*HH*CC];
__device__ float  g_cw[BB*HH*CC*DD];           // 2 MiB

// ---------------------------------------------------------------------------
// asm helpers
// ---------------------------------------------------------------------------
__device__ __forceinline__ uint32_t smem_u32(const void* p) {
    uint32_t a;
    asm("{ .reg .u64 t; cvta.to.shared.u64 t, %1; cvt.u32.u64 %0, t; }" : "=r"(a) : "l"(p));
    return a;
}
__device__ __forceinline__ void cp16(uint32_t dst, const void* src) {
    asm volatile("cp.async.cg.shared.global [%0], [%1], 16;" :: "r"(dst), "l"(src));
}
__device__ __forceinline__ void ldm4(uint32_t* r, uint32_t addr) {
    asm volatile("ldmatrix.sync.aligned.m8n8.x4.shared.b16 {%0,%1,%2,%3}, [%4];"
                 : "=r"(r[0]), "=r"(r[1]), "=r"(r[2]), "=r"(r[3]) : "r"(addr));
}
__device__ __forceinline__ void mma16816(float* c, const uint32_t* a, const uint32_t* b) {
    asm volatile("mma.sync.aligned.m16n8k16.row.col.f32.f16.f16.f32 "
                 "{%0,%1,%2,%3}, {%4,%5,%6,%7}, {%8,%9}, {%0,%1,%2,%3};"
                 : "+f"(c[0]), "+f"(c[1]), "+f"(c[2]), "+f"(c[3])
                 : "r"(a[0]), "r"(a[1]), "r"(a[2]), "r"(a[3]), "r"(b[0]), "r"(b[1]));
}
__device__ __forceinline__ float rcp_approx(float x) {
    float r;
    asm("rcp.approx.f32 %0, %1;" : "=f"(r) : "f"(x));
    return r;
}

// ---------------------------------------------------------------------------
// Fused prep: blocks [0, 8192) convert X fp32 -> fp16 (8 floats / thread);
// blocks [8192, 10240) transpose+convert W [K][N] fp32 -> g_Wt fp16 [N][K].
// ---------------------------------------------------------------------------
__global__ __launch_bounds__(256) void convXW(const float* __restrict__ X,
                                              const float* __restrict__ W) {
    const int tid = threadIdx.x;
    if (blockIdx.x < 8192) {
        size_t i = (size_t)blockIdx.x * 256 + tid;       // < 2M
        const float4* src = (const float4*)X + i * 2;
        float4 x0 = src[0], x1 = src[1];
        __half2 h0 = __floats2half2_rn(x0.x, x0.y);
        __half2 h1 = __floats2half2_rn(x0.z, x0.w);
        __half2 h2 = __floats2half2_rn(x1.x, x1.y);
        __half2 h3 = __floats2half2_rn(x1.z, x1.w);
        uint4 o;
        o.x = *(uint32_t*)&h0; o.y = *(uint32_t*)&h1;
        o.z = *(uint32_t*)&h2; o.w = *(uint32_t*)&h3;
        ((uint4*)g_Xh)[i] = o;
    } else {
        __shared__ float tile[32][33];
        const int bw = blockIdx.x - 8192;                // < 2048
        const int n0 = (bw & 63) * 32, k0 = (bw >> 6) * 32;
        const int tx = tid & 31, ty = tid >> 5;          // 32 x 8
        for (int r = ty; r < 32; r += 8)
            tile[r][tx] = W[(size_t)(k0 + r) * NN + n0 + tx];
        __syncthreads();
        for (int r = ty; r < 32; r += 8)
            g_Wt[(size_t)(n0 + r) * DIN + k0 + tx] = __float2half(tile[tx][r]);
    }
}

// ---------------------------------------------------------------------------
// GEMM via mma.sync: kv = relu(X @ W); fused: de-interleave v (fp16, smem-
// staged coalesced store), e = exp(q.relu(k)), and per-32-row-chunk prefix
// aggregates (u = sum e, w = sum e*v) — NO max stabilization (s bounded ~±4).
// CTA 256x128x64, 512 threads, 4-stage cp.async, B-fragment double buffer.
// blockIdx.x = head h, blockIdx.y = M-tile (256 rows = 8 scan chunks).
// ---------------------------------------------------------------------------
__device__ __forceinline__ void issue_stage(uint32_t sb, int stage, int kc,
                                            int bm, int bn, int tid) {
    const uint32_t so = sb + (uint32_t)stage * STAGE_BYTES;
    const int k0 = kc * GBK;
#pragma unroll
    for (int i = 0; i < 4; i++) {                        // A: 256 rows x 128B
        int idx = tid + i * 512;
        int row = idx >> 3, ch = idx & 7;
        cp16(so + row * 128 + ((uint32_t)(ch ^ (row & 7)) << 4),
             g_Xh + (size_t)(bm + row) * DIN + k0 + ch * 8);
    }
#pragma unroll
    for (int i = 0; i < 2; i++) {                        // B: 128 rows x 128B
        int idx = tid + i * 512;
        int row = idx >> 3, ch = idx & 7;
        cp16(so + 32768u + row * 128 + ((uint32_t)(ch ^ (row & 7)) << 4),
             g_Wt + (size_t)(bn + row) * DIN + k0 + ch * 8);
    }
}

__global__ __launch_bounds__(512) void gemm_mma(const float* __restrict__ qk) {
    extern __shared__ char sm[];
    __shared__ float sred[256][4];
    __shared__ float ssm[256];
    const uint32_t sb = smem_u32(sm);
    const int tid = threadIdx.x;
    const int wid = tid >> 5, lane = tid & 31;
    const int wm = wid >> 2, wn = wid & 3;               // 4 x 4 warps
    const int h  = blockIdx.x;
    const int bn = h << 7;
    const int bm = blockIdx.y * GBM;

    float acc[4][4][4];
#pragma unroll
    for (int a = 0; a < 4; a++)
#pragma unroll
        for (int b = 0; b < 4; b++)
#pragma unroll
            for (int c = 0; c < 4; c++) acc[a][b][c] = 0.f;

    // ldmatrix per-thread geometry
    const int arow = lane & 15;
    const int asel = lane >> 4;
    const int asw  = arow & 7;
    const int brow = (lane & 7) | (((lane >> 4) & 1) << 3);
    const int bsel = (lane >> 3) & 1;
    const int bsw  = brow & 7;
    uint32_t a_off[4], b_off[2];
#pragma unroll
    for (int mt = 0; mt < 4; mt++) a_off[mt] = (uint32_t)(wm * 64 + mt * 16 + arow) * 128;
#pragma unroll
    for (int bt = 0; bt < 2; bt++) b_off[bt] = 32768u + (uint32_t)(wn * 32 + bt * 16 + brow) * 128;

    // pipeline prologue
    for (int s = 0; s < STAGES - 1; s++) {
        issue_stage(sb, s, s, bm, bn, tid);
        asm volatile("cp.async.commit_group;" ::: "memory");
    }

    for (int kc = 0; kc < KITERS; kc++) {
        asm volatile("cp.async.wait_group 2;" ::: "memory");
        __syncthreads();

        if (kc + STAGES - 1 < KITERS)
            issue_stage(sb, (kc + STAGES - 1) & (STAGES - 1), kc + STAGES - 1, bm, bn, tid);
        asm volatile("cp.async.commit_group;" ::: "memory");

        const uint32_t so = sb + (uint32_t)(kc & (STAGES - 1)) * STAGE_BYTES;
        // B-fragment double buffer: prefetch ks+1 while issuing mma for ks
        uint32_t bf[2][2][4];
#pragma unroll
        for (int bt = 0; bt < 2; bt++)
            ldm4(bf[0][bt], so + b_off[bt] + ((uint32_t)(bsel ^ bsw) << 4));
#pragma unroll
        for (int ks = 0; ks < 4; ks++) {
            uint32_t af[4][4];
#pragma unroll
            for (int mt = 0; mt < 4; mt++)
                ldm4(af[mt], so + a_off[mt] + ((uint32_t)(((ks << 1) | asel) ^ asw) << 4));
            if (ks < 3) {
#pragma unroll
                for (int bt = 0; bt < 2; bt++)
                    ldm4(bf[(ks + 1) & 1][bt],
                         so + b_off[bt] + ((uint32_t)((((ks + 1) << 1) | bsel) ^ bsw) << 4));
            }
            const uint32_t (*bcur)[4] = bf[ks & 1];
#pragma unroll
            for (int mt = 0; mt < 4; mt++) {
                mma16816(acc[mt][0], af[mt], &bcur[0][0]);
                mma16816(acc[mt][1], af[mt], &bcur[0][2]);
                mma16816(acc[mt][2], af[mt], &bcur[1][0]);
                mma16816(acc[mt][3], af[mt], &bcur[1][2]);
            }
        }
    }

    // ------------- fused epilogue -------------
    // c0,c1 = (k,v) at row gq; c2,c3 = (k,v) at row gq+8; d = wn*16+nt*4+qd
    const int gq = lane >> 2, qd = lane & 3;
    float qv[4];
#pragma unroll
    for (int nt = 0; nt < 4; nt++)
        qv[nt] = __ldg(&qk[h * DD + wn * 16 + nt * 4 + qd]);

#pragma unroll
    for (int mt = 0; mt < 4; mt++) {
        const int ml0 = wm * 64 + mt * 16 + gq;
        float s0 = 0.f, s1 = 0.f;
#pragma unroll
        for (int nt = 0; nt < 4; nt++) {
            float k0 = fmaxf(acc[mt][nt][0], 0.f), v0 = fmaxf(acc[mt][nt][1], 0.f);
            float k1 = fmaxf(acc[mt][nt][2], 0.f), v1 = fmaxf(acc[mt][nt][3], 0.f);
            s0 += qv[nt] * k0;
            s1 += qv[nt] * k1;
            acc[mt][nt][1] = v0;                 // keep relu'd v for aggregates
            acc[mt][nt][3] = v1;
        }
        s0 += __shfl_xor_sync(0xFFFFFFFF, s0, 1);
        s0 += __shfl_xor_sync(0xFFFFFFFF, s0, 2);
        s1 += __shfl_xor_sync(0xFFFFFFFF, s1, 1);
        s1 += __shfl_xor_sync(0xFFFFFFFF, s1, 2);
        if (qd == 0) {
            sred[ml0][wn]     = s0;
            sred[ml0 + 8][wn] = s1;
        }
    }
    __syncthreads();
    if (tid < 256) {
        float s = sred[tid][0] + sred[tid][1] + sred[tid][2] + sred[tid][3];
        float e = __expf(s);                     // |s| ~ <= 5, no overflow risk
        g_s[(bm + tid) * HH + h] = e;
        ssm[tid] = e;
    }
    __syncthreads();

    // ---- per-chunk prefix aggregates at 32-row granularity (pure sums) ----
#pragma unroll
    for (int half = 0; half < 2; half++) {
        const int mtA = half * 2, mtB = half * 2 + 1;
        float eA0 = ssm[wm * 64 + mtA * 16 + gq];
        float eA1 = ssm[wm * 64 + mtA * 16 + gq + 8];
        float eB0 = ssm[wm * 64 + mtB * 16 + gq];
        float eB1 = ssm[wm * 64 + mtB * 16 + gq + 8];
        float lu = eA0 + eA1 + eB0 + eB1;
        float wv[4];
#pragma unroll
        for (int nt = 0; nt < 4; nt++)
            wv[nt] = eA0 * acc[mtA][nt][1] + eA1 * acc[mtA][nt][3]
                   + eB0 * acc[mtB][nt][1] + eB1 * acc[mtB][nt][3];
#pragma unroll
        for (int mask = 4; mask <= 16; mask <<= 1) {
            lu += __shfl_xor_sync(0xFFFFFFFF, lu, mask);
#pragma unroll
            for (int nt = 0; nt < 4; nt++)
                wv[nt] += __shfl_xor_sync(0xFFFFFFFF, wv[nt], mask);
        }
        const int crow = (bm >> 5) + wm * 2 + half;        // global 32-row chunk
        const int cidx = ((crow >> 7) * HH + h) * CC + (crow & 127);
        if (gq == 0) {
#pragma unroll
            for (int nt = 0; nt < 4; nt++)
                g_cw[cidx * DD + wn * 16 + nt * 4 + qd] = wv[nt];
            if (qd == 0 && wn == 0) g_cu[cidx] = lu;
        }
    }

    // ---- stage v (fp16) into now-idle pipeline smem, then coalesced write ----
    // layout: [256 rows][72 halfs] (144B stride: 16B-aligned, bank-shift 4/row)
    __half* svh = (__half*)sm;
#pragma unroll
    for (int mt = 0; mt < 4; mt++) {
        const int ml0 = wm * 64 + mt * 16 + gq;
#pragma unroll
        for (int nt = 0; nt < 4; nt++) {
            const int dl = wn * 16 + nt * 4 + qd;
            svh[ml0 * 72 + dl]       = __float2half_rn(acc[mt][nt][1]);
            svh[(ml0 + 8) * 72 + dl] = __float2half_rn(acc[mt][nt][3]);
        }
    }
    __syncthreads();
    const uint4* src4 = (const uint4*)sm;
#pragma unroll
    for (int i = 0; i < 4; i++) {
        int idx = tid + i * 512;                 // < 2048
        int row = idx >> 3, part = idx & 7;
        *((uint4*)(g_vh + (size_t)(bm + row) * (HH*DD) + h * DD + part * 8)) =
            src4[row * 9 + part];
    }
}

// ---------------------------------------------------------------------------
// Scan phase B: exclusive prefix SUM over chunk aggregates (CC=128) — pure
// FADD, no exp. grid = B*H, 64 threads.
// ---------------------------------------------------------------------------
__global__ __launch_bounds__(64) void scanB() {
    __shared__ float scu[CC], scw[CC * DD];              // 32.5 KB
    const int bh = blockIdx.x;
    const int d  = threadIdx.x;

    for (int c = 0; c < CC; c++)
        scw[c * DD + d] = g_cw[(size_t)(bh * CC + c) * DD + d];
    scu[d]      = g_cu[bh * CC + d];
    scu[d + 64] = g_cu[bh * CC + d + 64];
    __syncthreads();

    float uC = 0.f, wC = 0.f;
    for (int c = 0; c < CC; c++) {
        const int idx = bh * CC + c;
        const float ua = scu[c];
        const float wa = scw[c * DD + d];
        g_cw[(size_t)idx * DD + d] = wC;            // exclusive prefix out
        if (d == 0) g_cu[idx] = uC;
        uC += ua;
        wC += wa;
    }
}

// ---------------------------------------------------------------------------
// Scan phase C fused with head-reduction: out[b,t,d] = sum_h w/u with
// u,w pure prefix sums (e preloaded from g_s; NO exp, NO branch in the
// inner loop). grid = (B*CC, 2) = (1024 blocks), 128 threads
// (4 h-group warps x 32 d). Wave-local slab reduced+stored in-loop.
// ---------------------------------------------------------------------------
#define SCW  8                                  // tt per wave
#define NWAVE (LL/SCW)                          // 4
#define VWAVE_HALFS (SCW * HH * 32)             // 4096 halfs = 8KB

__global__ __launch_bounds__(128) void scanCR(float* __restrict__ out) {
    extern __shared__ float dyn[];
    __half* vbuf = (__half*)dyn;                         // 2 waves x 8KB
    float*  slab = dyn + (2 * VWAVE_HALFS) / 2;          // +4096 floats: 4KB slab
    float*  s_sm = slab + 4 * SCW * 32;                  // +1024 floats: 2KB e
    const int b     = blockIdx.x / CC;
    const int c     = blockIdx.x % CC;
    const int dhalf = blockIdx.y;                        // 0 or 1
    const int tid   = threadIdx.x;
    const int hs    = tid >> 5;                          // 0..3 (warp = h-group)
    const int dl    = tid & 31;                          // local d
    const int t0    = c * LL;

    const uint32_t vbase = smem_u32(vbuf);
    const __half* vsrc = g_vh + (size_t)(b * TT + t0) * (HH*DD) + dhalf * 32;

    // issue one 8-tt wave into buffer (wv & 1): 512 cp16, 4 per thread
    auto issue_wave = [&](int wv) {
        const uint32_t bofs = (uint32_t)((wv & 1) * VWAVE_HALFS * 2);
#pragma unroll
        for (int i = 0; i < 4; i++) {
            int idx = tid + i * 128;                     // < 512
            int ttl = idx >> 6, rem = idx & 63;
            int h = rem >> 2, seg = rem & 3;
            cp16(vbase + bofs + (uint32_t)(((ttl * HH + h) * 32 + seg * 8) * 2),
                 vsrc + (size_t)(wv * SCW + ttl) * (HH*DD) + h * DD + seg * 8);
        }
        asm volatile("cp.async.commit_group;" ::: "memory");
    };

    issue_wave(0);
    issue_wave(1);

    // stage e block: contiguous 512 floats (128 float4)
    ((float4*)s_sm)[tid] = ((const float4*)(g_s + (size_t)(b * TT + t0) * HH))[tid];

    float u[4], w[4];
#pragma unroll
    for (int hi = 0; hi < 4; hi++) {
        const int h   = hs * 4 + hi;
        const int idx = (b * HH + h) * CC + c;
        u[hi] = g_cu[idx];
        w[hi] = g_cw[(size_t)idx * DD + dhalf * 32 + dl];
    }

    float* myslab = slab + hs * SCW * 32;
    for (int wv = 0; wv < NWAVE; wv++) {
        if (wv < NWAVE - 2)
            asm volatile("cp.async.wait_group 1;" ::: "memory");
        else
            asm volatile("cp.async.wait_group 0;" ::: "memory");
        __syncthreads();    // also orders prev wave's slab reads before writes

        const __half* vb = vbuf + (wv & 1) * VWAVE_HALFS;
#pragma unroll
        for (int ttl = 0; ttl < SCW; ttl++) {
            const int tt = wv * SCW + ttl;
#pragma unroll
            for (int hi = 0; hi < 4; hi++) {
                const int h = hs * 4 + hi;
                const float e = s_sm[tt * HH + h];
                const float v = __half2float(vb[(ttl * HH + h) * 32 + dl]);
                u[hi] += e;
                w[hi] += e * v;
            }
            // one rcp for all four heads: 1/ui = prod(others) * rcp(prod(all))
            const float p01 = u[0] * u[1];
            const float p23 = u[2] * u[3];
            const float rp  = rcp_approx(p01 * p23);
            float sum = (w[0] * u[1] + w[1] * u[0]) * (rp * p23)
                      + (w[2] * u[3] + w[3] * u[2]) * (rp * p01);
            myslab[ttl * 32 + dl] = sum;
        }
        __syncthreads();                                  // slab complete, vbuf free
        if (wv + 2 < NWAVE) issue_wave(wv + 2);

        // reduce this wave's slab across the 4 h-groups and store (overlaps
        // the cp.async just issued). 256 outputs, 128 threads -> 2 each.
        for (int i = tid; i < SCW * 32; i += 128) {
            const int ttl = i >> 5, dd = i & 31;
            out[((size_t)b * TT + t0 + wv * SCW + ttl) * DD + dhalf * 32 + dd] =
                slab[i] + slab[SCW*32 + i] + slab[2*SCW*32 + i] + slab[3*SCW*32 + i];
        }
    }
}

extern "C" void kernel_launch(void* const* d_in, const int* in_sizes, int n_in,
                              void* d_out, int out_size) {
    const float* X = (const float*)d_in[0];   // [B,T,DIN]
    const float* W = (const float*)d_in[1];   // [DIN, 2048]
    const float* q = (const float*)d_in[2];   // [H,D]
    float* out = (float*)d_out;               // [B,T,D]

    const int gemm_smem = STAGES * (int)STAGE_BYTES;                 // 196608
    const int scan_smem = 2 * VWAVE_HALFS * 2                        // v ring 16KB
                        + 4 * SCW * 32 * (int)sizeof(float)          // slab  4KB
                        + LL * HH * (int)sizeof(float);              // e     2KB
    cudaFuncSetAttribute(gemm_mma, cudaFuncAttributeMaxDynamicSharedMemorySize,
                         gemm_smem);
    cudaFuncSetAttribute(scanCR, cudaFuncAttributeMaxDynamicSharedMemorySize,
                         scan_smem);

    convXW<<<8192 + 2048, 256>>>(X, W);
    gemm_mma<<<dim3(HH, MM / GBM), 512, gemm_smem>>>(q);
    scanB<<<BB * HH, 64>>>();
    scanCR<<<dim3(BB * CC, 2), 128, scan_smem>>>(out);
}